// round 4
// baseline (speedup 1.0000x reference)
#include <cuda_runtime.h>
#include <cuda_bf16.h>
#include <cstdint>

// Problem constants
#define B_  64
#define C_  3
#define H_  224
#define W_  224
#define GH  28
#define GW  28
#define D_  768
#define KD  192                 // C*8*8
#define M_  (B_*GH*GW)          // 50176

#define PX 512                  // absmax partial blocks for x
#define PW 32                   // absmax partial blocks for w

// ---- scratch (no cudaMalloc allowed) ----
__device__ float g_partials[PX + PW];
__device__ float g_scales[3];   // sx, sw, sx*sw

// ===========================================================================
// Pass 1: per-block absmax partials (no atomics, no zeroing needed)
// ===========================================================================
__global__ void absmax_part_kernel(const float4* __restrict__ x4,
                                   const float4* __restrict__ w4) {
    __shared__ float red[8];
    const float4* p;
    int n4, bid = blockIdx.x, nb;
    if (bid < PX) { p = x4; n4 = (B_*C_*H_*W_)/4; nb = PX; }
    else { p = w4; n4 = (D_*KD)/4; bid -= PX; nb = PW; }
    float m = 0.f;
    for (int i = bid * blockDim.x + threadIdx.x; i < n4; i += nb * blockDim.x) {
        float4 v = p[i];
        m = fmaxf(m, fmaxf(fmaxf(fabsf(v.x), fabsf(v.y)),
                           fmaxf(fabsf(v.z), fabsf(v.w))));
    }
#pragma unroll
    for (int o = 16; o > 0; o >>= 1)
        m = fmaxf(m, __shfl_xor_sync(0xffffffffu, m, o));
    if ((threadIdx.x & 31) == 0) red[threadIdx.x >> 5] = m;
    __syncthreads();
    if (threadIdx.x < 32) {
        float v = (threadIdx.x < 8) ? red[threadIdx.x] : 0.f;
#pragma unroll
        for (int o = 4; o > 0; o >>= 1)
            v = fmaxf(v, __shfl_xor_sync(0xffffffffu, v, o));
        if (threadIdx.x == 0) g_partials[blockIdx.x] = v;
    }
}

// ===========================================================================
// Pass 2: reduce partials -> scales (one block)
// ===========================================================================
__global__ void scale_kernel() {
    __shared__ float red[16];
    int t = threadIdx.x;                       // 512 threads
    float v = g_partials[t];
#pragma unroll
    for (int o = 16; o > 0; o >>= 1)
        v = fmaxf(v, __shfl_xor_sync(0xffffffffu, v, o));
    if ((t & 31) == 0) red[t >> 5] = v;
    __syncthreads();
    if (t < 32) {
        float mx = (t < 16) ? red[t] : 0.f;
#pragma unroll
        for (int o = 8; o > 0; o >>= 1)
            mx = fmaxf(mx, __shfl_xor_sync(0xffffffffu, mx, o));
        float wv = g_partials[PX + t];
#pragma unroll
        for (int o = 16; o > 0; o >>= 1)
            wv = fmaxf(wv, __shfl_xor_sync(0xffffffffu, wv, o));
        if (t == 0) {
            float sx = fmaxf(mx, 1e-8f) / 127.0f;
            float sw = fmaxf(wv, 1e-8f) / 127.0f;
            g_scales[0] = sx;
            g_scales[1] = sw;
            g_scales[2] = sx * sw;
        }
    }
}

// ===========================================================================
// Pass 3: fused quantize + patchify + GEMM + epilogue.
// out[M,768] = (fq(x) patchified @ fq(w)^T) * sx*sw + bias
// CTA tile 128(M) x 128(N), K=192 staged once in smem (pad stride 200 bf16),
// 8 warps, each 32(M) x 64(N), mma.sync m16n8k16 bf16, ldmatrix.x4 fragments.
// ===========================================================================
#define SSTRIDE 200                      // bf16 elems per smem row (400 B)
#define A_OFF   0
#define B_OFF   (128 * SSTRIDE * 2)      // 51200 B
#define BIAS_OFF (2 * 128 * SSTRIDE * 2) // 102400 B
#define GEMM_SMEM (BIAS_OFF + 512)

__device__ __forceinline__ float fq(float v, float s) {
    return rintf(fminf(fmaxf(v / s, -127.f), 127.f));
}
__device__ __forceinline__ unsigned int pack2(float a, float b, float s) {
    __nv_bfloat162 h = __floats2bfloat162_rn(fq(a, s), fq(b, s));
    return *reinterpret_cast<unsigned int*>(&h);
}
__device__ __forceinline__ uint32_t smem_u32(const void* p) {
    uint32_t a;
    asm("{ .reg .u64 t; cvta.to.shared.u64 t, %1; cvt.u32.u64 %0, t; }"
        : "=r"(a) : "l"(p));
    return a;
}

__global__ void __launch_bounds__(256, 2)
gemm_fused_kernel(const float* __restrict__ x, const float* __restrict__ w,
                  const float* __restrict__ bias, float* __restrict__ out) {
    extern __shared__ char smem[];
    char* a_ptr = smem + A_OFF;
    char* b_ptr = smem + B_OFF;
    float* bias_s = reinterpret_cast<float*>(smem + BIAS_OFF);

    const int tid = threadIdx.x;
    const int bn = blockIdx.x;   // 0..5
    const int bm = blockIdx.y;   // 0..391

    const float sx = g_scales[0];
    const float sw = g_scales[1];
    const float s  = g_scales[2];

    if (tid < 128) bias_s[tid] = bias[bn * 128 + tid];

    // ---- stage + quantize A (from x, patch gather) and B (from w) ----
    // 3072 runs each; run = 8 floats (one patch row / one w segment) -> 16 B
#pragma unroll
    for (int it = 0; it < 12; it++) {
        int cid = tid + it * 256;          // 0..3071
        int row = cid / 24, run = cid % 24;
        // A: patch gather
        {
            int m  = bm * 128 + row;
            int b  = m / (GH * GW);
            int rr = m % (GH * GW);
            int xb = rr / GW, wb = rr % GW;
            int c = run >> 3, p = run & 7;
            const float4* src = reinterpret_cast<const float4*>(
                x + (((size_t)(b * C_ + c) * H_ + xb * 8 + p) * W_ + wb * 8));
            float4 v0 = src[0], v1 = src[1];
            uint2 o0 = make_uint2(pack2(v0.x, v0.y, sx), pack2(v0.z, v0.w, sx));
            uint2 o1 = make_uint2(pack2(v1.x, v1.y, sx), pack2(v1.z, v1.w, sx));
            char* dst = a_ptr + row * (SSTRIDE * 2) + run * 16;
            *reinterpret_cast<uint2*>(dst)     = o0;
            *reinterpret_cast<uint2*>(dst + 8) = o1;
        }
        // B: straight rows of w
        {
            int n = bn * 128 + row;
            const float4* src = reinterpret_cast<const float4*>(
                w + (size_t)n * KD + run * 8);
            float4 v0 = src[0], v1 = src[1];
            uint2 o0 = make_uint2(pack2(v0.x, v0.y, sw), pack2(v0.z, v0.w, sw));
            uint2 o1 = make_uint2(pack2(v1.x, v1.y, sw), pack2(v1.z, v1.w, sw));
            char* dst = b_ptr + row * (SSTRIDE * 2) + run * 16;
            *reinterpret_cast<uint2*>(dst)     = o0;
            *reinterpret_cast<uint2*>(dst + 8) = o1;
        }
    }
    __syncthreads();

    // ---- MMA mainloop ----
    const int warp = tid >> 5, lane = tid & 31;
    const int wm = warp & 3;   // M sub-tile (32 rows)
    const int wn = warp >> 2;  // N sub-tile (64 cols)

    float acc[2][8][4];
#pragma unroll
    for (int i = 0; i < 2; i++)
#pragma unroll
        for (int j = 0; j < 8; j++)
#pragma unroll
            for (int r = 0; r < 4; r++) acc[i][j][r] = 0.f;

    // ldmatrix lane address components
    const uint32_t a_smem = smem_u32(a_ptr);
    const uint32_t b_smem = smem_u32(b_ptr);
    // A: row = wm*32 + i*16 + (lane&15); k-half = lane>>4
    const uint32_t a_lane_byte =
        (uint32_t)(wm * 32 + (lane & 15)) * (SSTRIDE * 2) + ((lane >> 4) << 4);
    // B: nrow = wn*64 + jj*16 + (grp>>1)*8 + (lane&7); k-half = grp&1
    const int grp = lane >> 3;
    const uint32_t b_lane_byte =
        (uint32_t)(wn * 64 + ((grp >> 1) << 3) + (lane & 7)) * (SSTRIDE * 2) +
        ((grp & 1) << 4);

#pragma unroll
    for (int ks = 0; ks < 12; ks++) {
        const uint32_t kb = (uint32_t)ks * 32;   // 16 bf16 = 32 B per k-step
        uint32_t a[2][4];
#pragma unroll
        for (int i = 0; i < 2; i++) {
            uint32_t addr = a_smem + a_lane_byte + (uint32_t)i * (16 * SSTRIDE * 2) + kb;
            asm volatile(
                "ldmatrix.sync.aligned.m8n8.x4.shared.b16 {%0,%1,%2,%3}, [%4];"
                : "=r"(a[i][0]), "=r"(a[i][1]), "=r"(a[i][2]), "=r"(a[i][3])
                : "r"(addr));
        }
#pragma unroll
        for (int jj = 0; jj < 4; jj++) {
            uint32_t bq[4];
            uint32_t addr = b_smem + b_lane_byte + (uint32_t)jj * (16 * SSTRIDE * 2) + kb;
            asm volatile(
                "ldmatrix.sync.aligned.m8n8.x4.shared.b16 {%0,%1,%2,%3}, [%4];"
                : "=r"(bq[0]), "=r"(bq[1]), "=r"(bq[2]), "=r"(bq[3])
                : "r"(addr));
#pragma unroll
            for (int i = 0; i < 2; i++) {
                asm volatile(
                    "mma.sync.aligned.m16n8k16.row.col.f32.bf16.bf16.f32 "
                    "{%0,%1,%2,%3}, {%4,%5,%6,%7}, {%8,%9}, {%0,%1,%2,%3};\n"
                    : "+f"(acc[i][jj*2][0]), "+f"(acc[i][jj*2][1]),
                      "+f"(acc[i][jj*2][2]), "+f"(acc[i][jj*2][3])
                    : "r"(a[i][0]), "r"(a[i][1]), "r"(a[i][2]), "r"(a[i][3]),
                      "r"(bq[0]), "r"(bq[1]));
                asm volatile(
                    "mma.sync.aligned.m16n8k16.row.col.f32.bf16.bf16.f32 "
                    "{%0,%1,%2,%3}, {%4,%5,%6,%7}, {%8,%9}, {%0,%1,%2,%3};\n"
                    : "+f"(acc[i][jj*2+1][0]), "+f"(acc[i][jj*2+1][1]),
                      "+f"(acc[i][jj*2+1][2]), "+f"(acc[i][jj*2+1][3])
                    : "r"(a[i][0]), "r"(a[i][1]), "r"(a[i][2]), "r"(a[i][3]),
                      "r"(bq[2]), "r"(bq[3]));
            }
        }
    }

    // ---- epilogue: scale + bias, float2 stores ----
    const int g = lane >> 2, t = lane & 3;
    const int m_base = bm * 128 + wm * 32;
    const int n_base = bn * 128 + wn * 64;
#pragma unroll
    for (int i = 0; i < 2; i++) {
        int row0 = m_base + i * 16 + g;
#pragma unroll
        for (int j = 0; j < 8; j++) {
            int col = n_base + j * 8 + t * 2;
            int lcol = wn * 64 + j * 8 + t * 2;
            float2 bv = *reinterpret_cast<const float2*>(&bias_s[lcol]);
            float2 v0 = make_float2(acc[i][j][0] * s + bv.x,
                                    acc[i][j][1] * s + bv.y);
            float2 v1 = make_float2(acc[i][j][2] * s + bv.x,
                                    acc[i][j][3] * s + bv.y);
            *reinterpret_cast<float2*>(&out[(size_t)row0 * D_ + col]) = v0;
            *reinterpret_cast<float2*>(&out[(size_t)(row0 + 8) * D_ + col]) = v1;
        }
    }
}

// ===========================================================================
extern "C" void kernel_launch(void* const* d_in, const int* in_sizes, int n_in,
                              void* d_out, int out_size) {
    (void)in_sizes; (void)n_in; (void)out_size;
    const float* x = (const float*)d_in[0];
    const float* w = (const float*)d_in[1];
    const float* b = (const float*)d_in[2];
    float* out = (float*)d_out;

    absmax_part_kernel<<<PX + PW, 256>>>((const float4*)x, (const float4*)w);
    scale_kernel<<<1, 512>>>();

    cudaFuncSetAttribute(gemm_fused_kernel,
                         cudaFuncAttributeMaxDynamicSharedMemorySize, GEMM_SMEM);
    dim3 grid(D_ / 128, M_ / 128);  // (6, 392)
    gemm_fused_kernel<<<grid, 256, GEMM_SMEM>>>(x, w, b, out);
}

// round 5
// speedup vs baseline: 1.8788x; 1.8788x over previous
#include <cuda_runtime.h>
#include <cuda_bf16.h>
#include <cstdint>

// Problem constants
#define B_  64
#define C_  3
#define H_  224
#define W_  224
#define GH  28
#define GW  28
#define D_  768
#define KD  192                 // C*8*8
#define M_  (B_*GH*GW)          // 50176

#define PX 588                  // x: 2408448 float4 / (588*256) = 16 iters exactly
#define PW 36                   // w: 36864 float4 / (36*256) = 4 iters exactly

// ---- scratch (no cudaMalloc allowed) ----
__device__ float g_partials[PX + PW];
__device__ float g_scales[3];                              // sx, sw, sx*sw
__device__ __nv_bfloat16 g_xq[(size_t)M_ * KD];            // 19.3 MB
__device__ __nv_bfloat16 g_wq[(size_t)D_ * KD];            // 288 KB

// ===========================================================================
// Pass 1: per-block absmax partials (no atomics; 4-way unrolled for MLP)
// ===========================================================================
__device__ __forceinline__ float amax4(float4 v) {
    return fmaxf(fmaxf(fabsf(v.x), fabsf(v.y)), fmaxf(fabsf(v.z), fabsf(v.w)));
}

__global__ void absmax_part_kernel(const float4* __restrict__ x4,
                                   const float4* __restrict__ w4) {
    __shared__ float red[8];
    const float4* p;
    int iters, bid = blockIdx.x, stride;
    if (bid < PX) { p = x4; iters = 4; stride = PX * 256; }        // 4 groups of 4
    else { p = w4; iters = 1; stride = PW * 256; bid -= PX; }      // 1 group of 4
    int i = bid * 256 + threadIdx.x;
    float m = 0.f;
    for (int g = 0; g < iters; g++) {
        float4 v0 = p[i];
        float4 v1 = p[i + stride];
        float4 v2 = p[i + 2 * stride];
        float4 v3 = p[i + 3 * stride];
        m = fmaxf(m, fmaxf(fmaxf(amax4(v0), amax4(v1)),
                           fmaxf(amax4(v2), amax4(v3))));
        i += 4 * stride;
    }
#pragma unroll
    for (int o = 16; o > 0; o >>= 1)
        m = fmaxf(m, __shfl_xor_sync(0xffffffffu, m, o));
    if ((threadIdx.x & 31) == 0) red[threadIdx.x >> 5] = m;
    __syncthreads();
    if (threadIdx.x < 32) {
        float v = (threadIdx.x < 8) ? red[threadIdx.x] : 0.f;
#pragma unroll
        for (int o = 4; o > 0; o >>= 1)
            v = fmaxf(v, __shfl_xor_sync(0xffffffffu, v, o));
        if (threadIdx.x == 0) g_partials[blockIdx.x] = v;
    }
}

// ===========================================================================
// Pass 2: reduce partials -> scales (one block, 640 threads)
// ===========================================================================
__global__ void scale_kernel() {
    __shared__ float redx[20], redw[20];
    int t = threadIdx.x;
    float v = (t < PX + PW) ? g_partials[t] : 0.f;
    float xv = (t < PX) ? v : 0.f;
    float wv = (t >= PX) ? v : 0.f;
#pragma unroll
    for (int o = 16; o > 0; o >>= 1) {
        xv = fmaxf(xv, __shfl_xor_sync(0xffffffffu, xv, o));
        wv = fmaxf(wv, __shfl_xor_sync(0xffffffffu, wv, o));
    }
    if ((t & 31) == 0) { redx[t >> 5] = xv; redw[t >> 5] = wv; }
    __syncthreads();
    if (t < 32) {
        float a = (t < 20) ? redx[t] : 0.f;
        float b = (t < 20) ? redw[t] : 0.f;
#pragma unroll
        for (int o = 16; o > 0; o >>= 1) {
            a = fmaxf(a, __shfl_xor_sync(0xffffffffu, a, o));
            b = fmaxf(b, __shfl_xor_sync(0xffffffffu, b, o));
        }
        if (t == 0) {
            float sx = fmaxf(a, 1e-8f) / 127.0f;
            float sw = fmaxf(b, 1e-8f) / 127.0f;
            g_scales[0] = sx;
            g_scales[1] = sw;
            g_scales[2] = sx * sw;
        }
    }
}

// ===========================================================================
// Pass 3: quantize w (copy) + x (patchify) -> bf16, one launch, coalesced
// ===========================================================================
__device__ __forceinline__ float fq(float v, float s) {
    return rintf(fminf(fmaxf(v / s, -127.f), 127.f));
}
__device__ __forceinline__ unsigned int pack2(float a, float b, float s) {
    __nv_bfloat162 h = __floats2bfloat162_rn(fq(a, s), fq(b, s));
    return *reinterpret_cast<unsigned int*>(&h);
}

#define WQBLOCKS 144   // 144*256 = 36864 = D_*KD/4
#define XQBLOCKS 4704  // 4704*256 = 1204224 = B_*C_*H_*GW

__global__ void quant_kernel(const float* __restrict__ x,
                             const float* __restrict__ w) {
    int bid = blockIdx.x;
    if (bid < WQBLOCKS) {
        float s = g_scales[1];
        int i = bid * 256 + threadIdx.x;
        float4 v = reinterpret_cast<const float4*>(w)[i];
        uint2 o;
        o.x = pack2(v.x, v.y, s);
        o.y = pack2(v.z, v.w, s);
        reinterpret_cast<uint2*>(g_wq)[i] = o;
    } else {
        float s = g_scales[0];
        int tid = (bid - WQBLOCKS) * 256 + threadIdx.x;
        int wb = tid % GW;
        int h  = (tid / GW) % H_;
        int c  = (tid / (GW * H_)) % C_;
        int b  = tid / (GW * H_ * C_);
        const float4* src = reinterpret_cast<const float4*>(
            x + ((((size_t)b * C_ + c) * H_ + h) * W_ + (size_t)wb * 8));
        float4 v0 = src[0], v1 = src[1];
        int xb = h >> 3, p = h & 7;
        size_t m = (size_t)b * (GH * GW) + (size_t)xb * GW + wb;
        size_t k = (size_t)c * 64 + (size_t)p * 8;
        uint4 o;
        o.x = pack2(v0.x, v0.y, s);
        o.y = pack2(v0.z, v0.w, s);
        o.z = pack2(v1.x, v1.y, s);
        o.w = pack2(v1.z, v1.w, s);
        *reinterpret_cast<uint4*>(g_xq + m * KD + k) = o;
    }
}

// ===========================================================================
// Pass 4: GEMM. out[M,768] = (xq @ wq^T) * s + bias
// CTA tile 128(M) x 128(N), K=192 staged once (pad stride 200 bf16),
// 8 warps each 32(M) x 64(N), ldmatrix.x4 + mma.sync m16n8k16 bf16.
// ===========================================================================
#define SSTRIDE 200                      // bf16 elems per smem row (400 B)
#define A_OFF   0
#define B_OFF   (128 * SSTRIDE * 2)      // 51200 B
#define BIAS_OFF (2 * 128 * SSTRIDE * 2) // 102400 B
#define GEMM_SMEM (BIAS_OFF + 512)

__device__ __forceinline__ uint32_t smem_u32(const void* p) {
    uint32_t a;
    asm("{ .reg .u64 t; cvta.to.shared.u64 t, %1; cvt.u32.u64 %0, t; }"
        : "=r"(a) : "l"(p));
    return a;
}

__global__ void __launch_bounds__(256, 2)
gemm_kernel(const float* __restrict__ bias, float* __restrict__ out) {
    extern __shared__ char smem[];
    char* a_ptr = smem + A_OFF;
    char* b_ptr = smem + B_OFF;
    float* bias_s = reinterpret_cast<float*>(smem + BIAS_OFF);

    const int tid = threadIdx.x;
    const int bn = blockIdx.x;   // 0..5
    const int bm = blockIdx.y;   // 0..391
    const float s = g_scales[2];

    if (tid < 128) bias_s[tid] = bias[bn * 128 + tid];

    // ---- stage A,B tiles: coalesced uint4 from g_xq / g_wq ----
    const uint4* gA = reinterpret_cast<const uint4*>(g_xq + (size_t)bm * 128 * KD);
    const uint4* gB = reinterpret_cast<const uint4*>(g_wq + (size_t)bn * 128 * KD);
#pragma unroll
    for (int it = 0; it < 12; it++) {
        int cid = tid + it * 256;            // 0..3071
        int row = cid / 24, cc = cid % 24;   // 16B vector within 192-elem row
        char* da = a_ptr + row * (SSTRIDE * 2) + cc * 16;
        char* db = b_ptr + row * (SSTRIDE * 2) + cc * 16;
        *reinterpret_cast<uint4*>(da) = gA[cid];
        *reinterpret_cast<uint4*>(db) = gB[cid];
    }
    __syncthreads();

    // ---- MMA mainloop (validated in R4) ----
    const int warp = tid >> 5, lane = tid & 31;
    const int wm = warp & 3;   // M sub-tile (32 rows)
    const int wn = warp >> 2;  // N sub-tile (64 cols)

    float acc[2][8][4];
#pragma unroll
    for (int i = 0; i < 2; i++)
#pragma unroll
        for (int j = 0; j < 8; j++)
#pragma unroll
            for (int r = 0; r < 4; r++) acc[i][j][r] = 0.f;

    const uint32_t a_smem = smem_u32(a_ptr);
    const uint32_t b_smem = smem_u32(b_ptr);
    const uint32_t a_lane_byte =
        (uint32_t)(wm * 32 + (lane & 15)) * (SSTRIDE * 2) + ((lane >> 4) << 4);
    const int grp = lane >> 3;
    const uint32_t b_lane_byte =
        (uint32_t)(wn * 64 + ((grp >> 1) << 3) + (lane & 7)) * (SSTRIDE * 2) +
        ((grp & 1) << 4);

#pragma unroll
    for (int ks = 0; ks < 12; ks++) {
        const uint32_t kb = (uint32_t)ks * 32;   // 16 bf16 = 32 B per k-step
        uint32_t a[2][4];
#pragma unroll
        for (int i = 0; i < 2; i++) {
            uint32_t addr = a_smem + a_lane_byte + (uint32_t)i * (16 * SSTRIDE * 2) + kb;
            asm volatile(
                "ldmatrix.sync.aligned.m8n8.x4.shared.b16 {%0,%1,%2,%3}, [%4];"
                : "=r"(a[i][0]), "=r"(a[i][1]), "=r"(a[i][2]), "=r"(a[i][3])
                : "r"(addr));
        }
#pragma unroll
        for (int jj = 0; jj < 4; jj++) {
            uint32_t bq[4];
            uint32_t addr = b_smem + b_lane_byte + (uint32_t)jj * (16 * SSTRIDE * 2) + kb;
            asm volatile(
                "ldmatrix.sync.aligned.m8n8.x4.shared.b16 {%0,%1,%2,%3}, [%4];"
                : "=r"(bq[0]), "=r"(bq[1]), "=r"(bq[2]), "=r"(bq[3])
                : "r"(addr));
#pragma unroll
            for (int i = 0; i < 2; i++) {
                asm volatile(
                    "mma.sync.aligned.m16n8k16.row.col.f32.bf16.bf16.f32 "
                    "{%0,%1,%2,%3}, {%4,%5,%6,%7}, {%8,%9}, {%0,%1,%2,%3};\n"
                    : "+f"(acc[i][jj*2][0]), "+f"(acc[i][jj*2][1]),
                      "+f"(acc[i][jj*2][2]), "+f"(acc[i][jj*2][3])
                    : "r"(a[i][0]), "r"(a[i][1]), "r"(a[i][2]), "r"(a[i][3]),
                      "r"(bq[0]), "r"(bq[1]));
                asm volatile(
                    "mma.sync.aligned.m16n8k16.row.col.f32.bf16.bf16.f32 "
                    "{%0,%1,%2,%3}, {%4,%5,%6,%7}, {%8,%9}, {%0,%1,%2,%3};\n"
                    : "+f"(acc[i][jj*2+1][0]), "+f"(acc[i][jj*2+1][1]),
                      "+f"(acc[i][jj*2+1][2]), "+f"(acc[i][jj*2+1][3])
                    : "r"(a[i][0]), "r"(a[i][1]), "r"(a[i][2]), "r"(a[i][3]),
                      "r"(bq[2]), "r"(bq[3]));
            }
        }
    }

    // ---- epilogue: scale + bias, float2 stores ----
    const int g = lane >> 2, t = lane & 3;
    const int m_base = bm * 128 + wm * 32;
    const int n_base = bn * 128 + wn * 64;
#pragma unroll
    for (int i = 0; i < 2; i++) {
        int row0 = m_base + i * 16 + g;
#pragma unroll
        for (int j = 0; j < 8; j++) {
            int col = n_base + j * 8 + t * 2;
            int lcol = wn * 64 + j * 8 + t * 2;
            float2 bv = *reinterpret_cast<const float2*>(&bias_s[lcol]);
            float2 v0 = make_float2(acc[i][j][0] * s + bv.x,
                                    acc[i][j][1] * s + bv.y);
            float2 v1 = make_float2(acc[i][j][2] * s + bv.x,
                                    acc[i][j][3] * s + bv.y);
            *reinterpret_cast<float2*>(&out[(size_t)row0 * D_ + col]) = v0;
            *reinterpret_cast<float2*>(&out[(size_t)(row0 + 8) * D_ + col]) = v1;
        }
    }
}

// ===========================================================================
extern "C" void kernel_launch(void* const* d_in, const int* in_sizes, int n_in,
                              void* d_out, int out_size) {
    (void)in_sizes; (void)n_in; (void)out_size;
    const float* x = (const float*)d_in[0];
    const float* w = (const float*)d_in[1];
    const float* b = (const float*)d_in[2];
    float* out = (float*)d_out;

    absmax_part_kernel<<<PX + PW, 256>>>((const float4*)x, (const float4*)w);
    scale_kernel<<<1, 640>>>();
    quant_kernel<<<WQBLOCKS + XQBLOCKS, 256>>>(x, w);

    cudaFuncSetAttribute(gemm_kernel,
                         cudaFuncAttributeMaxDynamicSharedMemorySize, GEMM_SMEM);
    dim3 grid(D_ / 128, M_ / 128);  // (6, 392)
    gemm_kernel<<<grid, 256, GEMM_SMEM>>>(b, out);
}